// round 1
// baseline (speedup 1.0000x reference)
#include <cuda_runtime.h>
#include <math.h>

// ---------------- problem constants ----------------
#define Nn 4096           // n = B*H*W
#define Dd 64             // latent dim
#define HKk 256
#define BM 128            // rows per block
#define BN 128            // cols per tile
#define NRB 32            // row blocks (N/BM)
#define NCB 4             // column chunks
#define CHUNK 1024        // cols per chunk
#define TPC 8             // tiles per chunk
#define OUTPLANE 262144   // B*C*H*W

// ---------------- static device scratch (no allocs allowed) ----------------
__device__ float g_zf[Nn*Dd];
__device__ float g_zs[Nn*Dd];
__device__ float g_zf2[Nn], g_zs2[Nn], g_phi1[Nn], g_phi2[Nn];
__device__ float g_w1m[Dd], g_w2m[Dd], g_b1m, g_b2m;
__device__ float g_r_m[NCB*Nn], g_r_s[NCB*Nn], g_r_bc[NCB*Nn];
__device__ int   g_r_bj[NCB*Nn];
__device__ float g_c_m[NRB*Nn], g_c_s[NRB*Nn];
__device__ int   g_idx[Nn];
__device__ float g_lse1[Nn], g_lse2[Nn];

// ---------------- k0: column-means of w1/w2 and means of b1/b2 ----------------
__global__ void k0(const float* __restrict__ w1, const float* __restrict__ b1,
                   const float* __restrict__ w2, const float* __restrict__ b2) {
    int d = threadIdx.x;  // 64 threads
    if (d < Dd) {
        float s1 = 0.f, s2 = 0.f;
        for (int k = 0; k < HKk; ++k) { s1 += w1[d*HKk + k]; s2 += w2[d*HKk + k]; }
        g_w1m[d] = s1 / (float)HKk;
        g_w2m[d] = s2 / (float)HKk;
    }
    if (d == 0) { float s = 0.f; for (int k = 0; k < HKk; ++k) s += b1[k]; g_b1m = s / (float)HKk; }
    if (d == 1) { float s = 0.f; for (int k = 0; k < HKk; ++k) s += b2[k]; g_b2m = s / (float)HKk; }
}

// ---------------- k_tr: transpose z (1024 x 256) -> zf (4096 x 64 row-major) ----------------
// z viewed as A[row=(b*64+c)][col=(h*16+w)]; zf linear = col*1024 + row.
__global__ void k_tr(const float* __restrict__ z) {
    __shared__ float t[32][33];
    int bx = blockIdx.x;  // col tile 0..7
    int by = blockIdx.y;  // row tile 0..31
    int x = bx*32 + threadIdx.x;
    #pragma unroll
    for (int q = 0; q < 4; ++q) {
        int row = by*32 + threadIdx.y + q*8;
        t[threadIdx.y + q*8][threadIdx.x] = z[row*256 + x];
    }
    __syncthreads();
    #pragma unroll
    for (int q = 0; q < 4; ++q) {
        int col = bx*32 + threadIdx.y + q*8;
        int row = by*32 + threadIdx.x;
        g_zf[col*1024 + row] = t[threadIdx.x][threadIdx.y + q*8];
    }
}

// ---------------- k1: zs = mu + exp(logvar)*noise, norms, phi1/phi2 ----------------
// one warp per row, 4 rows per 128-thread block
__global__ void k1(const float* __restrict__ codebook, const float* __restrict__ noise) {
    int warp = threadIdx.x >> 5, lane = threadIdx.x & 31;
    int row = blockIdx.x*4 + warp;
    const float* crow = codebook + (row >> 3) * (2*Dd);
    const float* nrow = noise + row*Dd;
    const float* frow = g_zf + row*Dd;
    float zs2 = 0.f, p1 = 0.f, zf2 = 0.f, p2 = 0.f;
    #pragma unroll
    for (int q = 0; q < 2; ++q) {
        int d = lane + q*32;
        float mu  = crow[d];
        float cov = expf(crow[Dd + d]);
        float zs  = mu + cov * nrow[d];
        g_zs[row*Dd + d] = zs;
        zs2 += zs*zs;
        p1  += zs * g_w1m[d];
        float zf = frow[d];
        zf2 += zf*zf;
        p2  += zf * g_w2m[d];
    }
    #pragma unroll
    for (int o = 16; o > 0; o >>= 1) {
        zs2 += __shfl_xor_sync(0xffffffffu, zs2, o);
        p1  += __shfl_xor_sync(0xffffffffu, p1,  o);
        zf2 += __shfl_xor_sync(0xffffffffu, zf2, o);
        p2  += __shfl_xor_sync(0xffffffffu, p2,  o);
    }
    if (lane == 0) {
        g_zs2[row] = zs2;  g_phi1[row] = p1 + g_b1m;
        g_zf2[row] = zf2;  g_phi2[row] = p2 + g_b2m;
    }
}

// ---------------- k2: fused cost GEMM + argmin + row-LSE + col-LSE partials ----------------
// smem layout (floats): zfs[0,8192) K-major [k*128+row] | zss[8192,16384) [k*128+col]
//                       zf2s[16384..16512) phi2s[..16640) zs2s[..16768) phi1s[..16896)
#define SMEM_FLOATS 16896
__global__ void __launch_bounds__(256, 1) k2() {
    extern __shared__ float sm[];
    float* zfs   = sm;
    float* zss   = sm + 8192;
    float* zf2s  = sm + 16384;
    float* phi2s = zf2s + 128;
    float* zs2s  = phi2s + 128;
    float* phi1s = zs2s + 128;

    const int tid = threadIdx.x;
    const int tx = tid & 15, ty = tid >> 4;
    const int rb = blockIdx.x, cb = blockIdx.y;
    const int i0 = rb * BM;

    // load zf tile transposed into K-major smem
    for (int t = tid; t < 128*16; t += 256) {
        int r = t >> 4, d4 = t & 15;
        float4 v = ((const float4*)g_zf)[(i0 + r)*16 + d4];
        zfs[(d4*4+0)*BM + r] = v.x;
        zfs[(d4*4+1)*BM + r] = v.y;
        zfs[(d4*4+2)*BM + r] = v.z;
        zfs[(d4*4+3)*BM + r] = v.w;
    }
    if (tid < BM) { zf2s[tid] = g_zf2[i0 + tid]; phi2s[tid] = g_phi2[i0 + tid]; }

    float rm[8], rs[8], bc[8]; int bj[8];
    #pragma unroll
    for (int r = 0; r < 8; ++r) { rm[r] = -1e30f; rs[r] = 0.f; bc[r] = 1e30f; bj[r] = 0x7fffffff; }

    for (int tile = 0; tile < TPC; ++tile) {
        const int j0 = cb*CHUNK + tile*BN;
        __syncthreads();  // zss free (prev reducers done) + first-iter zfs ready
        for (int t = tid; t < 128*16; t += 256) {
            int c = t >> 4, d4 = t & 15;
            float4 v = ((const float4*)g_zs)[(j0 + c)*16 + d4];
            zss[(d4*4+0)*BN + c] = v.x;
            zss[(d4*4+1)*BN + c] = v.y;
            zss[(d4*4+2)*BN + c] = v.z;
            zss[(d4*4+3)*BN + c] = v.w;
        }
        if (tid < BN) { zs2s[tid] = g_zs2[j0 + tid]; phi1s[tid] = g_phi1[j0 + tid]; }
        __syncthreads();

        float acc[8][8];
        #pragma unroll
        for (int r = 0; r < 8; ++r)
            #pragma unroll
            for (int c = 0; c < 8; ++c) acc[r][c] = 0.f;

        #pragma unroll 8
        for (int k = 0; k < Dd; ++k) {
            const float4 a0 = *(const float4*)(zfs + k*BM + ty*8);
            const float4 a1 = *(const float4*)(zfs + k*BM + ty*8 + 4);
            const float4 b0 = *(const float4*)(zss + k*BN + tx*8);
            const float4 b1 = *(const float4*)(zss + k*BN + tx*8 + 4);
            float av[8] = {a0.x, a0.y, a0.z, a0.w, a1.x, a1.y, a1.z, a1.w};
            float bv[8] = {b0.x, b0.y, b0.z, b0.w, b1.x, b1.y, b1.z, b1.w};
            #pragma unroll
            for (int r = 0; r < 8; ++r)
                #pragma unroll
                for (int c = 0; c < 8; ++c)
                    acc[r][c] += av[r] * bv[c];
        }

        // epilogue: cost, argmin, online LSE both sides
        float zs2v[8], p1v[8];
        #pragma unroll
        for (int c = 0; c < 8; ++c) { zs2v[c] = zs2s[tx*8 + c]; p1v[c] = phi1s[tx*8 + c]; }
        float cm[8], cs[8];
        #pragma unroll
        for (int c = 0; c < 8; ++c) { cm[c] = -1e30f; cs[c] = 0.f; }

        #pragma unroll
        for (int r = 0; r < 8; ++r) {
            const float zf2v = zf2s[ty*8 + r];
            const float p2v  = phi2s[ty*8 + r];
            #pragma unroll
            for (int c = 0; c < 8; ++c) {
                float cost = zf2v + zs2v[c] - 2.0f*acc[r][c];
                int j = j0 + tx*8 + c;
                if (cost < bc[r]) { bc[r] = cost; bj[r] = j; }
                float e1 = (p1v[c] - cost) * 10.0f;
                if (e1 > rm[r]) { rs[r] = rs[r]*__expf(rm[r] - e1) + 1.0f; rm[r] = e1; }
                else            { rs[r] += __expf(e1 - rm[r]); }
                float e2 = (p2v - cost) * 10.0f;
                if (e2 > cm[c]) { cs[c] = cs[c]*__expf(cm[c] - e2) + 1.0f; cm[c] = e2; }
                else            { cs[c] += __expf(e2 - cm[c]); }
            }
        }

        // column flush: reduce (cm,cs) across ty (16 partials per column), overlay on zss
        __syncthreads();
        float* redm = zss;
        float* reds = zss + 2048;
        #pragma unroll
        for (int c = 0; c < 8; ++c) {
            redm[(tx*8 + c)*16 + ty] = cm[c];
            reds[(tx*8 + c)*16 + ty] = cs[c];
        }
        __syncthreads();
        if (tid < BN) {
            float m = -1e30f, s = 0.f;
            #pragma unroll
            for (int t = 0; t < 16; ++t) {
                float mm = redm[tid*16 + t], ss = reds[tid*16 + t];
                if (mm > m) { s = s*__expf(m - mm) + ss; m = mm; }
                else        { s += ss*__expf(mm - m); }
            }
            g_c_m[rb*Nn + j0 + tid] = m;
            g_c_s[rb*Nn + j0 + tid] = s;
        }
    }

    // row flush: reduce (rm,rs,bc,bj) across tx (16 partials per row), overlay on zss
    __syncthreads();
    float* rrm = zss;
    float* rrs = zss + 2048;
    float* rrb = zss + 4096;
    int*   rrj = (int*)(zss + 6144);
    #pragma unroll
    for (int r = 0; r < 8; ++r) {
        int pos = (ty*8 + r)*16 + tx;
        rrm[pos] = rm[r]; rrs[pos] = rs[r]; rrb[pos] = bc[r]; rrj[pos] = bj[r];
    }
    __syncthreads();
    if (tid < BM) {
        float m = -1e30f, s = 0.f, bcv = 1e30f; int bjv = 0x7fffffff;
        #pragma unroll
        for (int t = 0; t < 16; ++t) {
            float mm = rrm[tid*16 + t], ss = rrs[tid*16 + t];
            if (mm > m) { s = s*__expf(m - mm) + ss; m = mm; }
            else        { s += ss*__expf(mm - m); }
            float bb = rrb[tid*16 + t]; int jj = rrj[tid*16 + t];
            if (bb < bcv || (bb == bcv && jj < bjv)) { bcv = bb; bjv = jj; }
        }
        g_r_m [cb*Nn + i0 + tid] = m;
        g_r_s [cb*Nn + i0 + tid] = s;
        g_r_bc[cb*Nn + i0 + tid] = bcv;
        g_r_bj[cb*Nn + i0 + tid] = bjv;
    }
}

// ---------------- k3: merge partials -> lse1, idx, lse2 ----------------
__global__ void k3() {
    int i = blockIdx.x*blockDim.x + threadIdx.x;  // 0..4095
    // rows (NCB partials): lse1, argmin (tie-break: smaller j)
    float m = -1e30f, s = 0.f, bcv = 1e30f; int bjv = 0x7fffffff;
    #pragma unroll
    for (int c = 0; c < NCB; ++c) {
        float mm = g_r_m[c*Nn + i], ss = g_r_s[c*Nn + i];
        if (mm > m) { s = s*__expf(m - mm) + ss; m = mm; }
        else        { s += ss*__expf(mm - m); }
        float bb = g_r_bc[c*Nn + i]; int jj = g_r_bj[c*Nn + i];
        if (bb < bcv || (bb == bcv && jj < bjv)) { bcv = bb; bjv = jj; }
    }
    g_lse1[i] = m + logf(s) - logf((float)Nn);   // includes wY=1/n weight inside log
    g_idx[i] = bjv;
    // columns (NRB partials): lse2
    m = -1e30f; s = 0.f;
    #pragma unroll
    for (int r = 0; r < NRB; ++r) {
        float mm = g_c_m[r*Nn + i], ss = g_c_s[r*Nn + i];
        if (mm > m) { s = s*__expf(m - mm) + ss; m = mm; }
        else        { s += ss*__expf(mm - m); }
    }
    g_lse2[i] = m + logf(s);
}

// ---------------- k4: loss + perplexity ----------------
__global__ void k4(float* __restrict__ out) {
    __shared__ double red[512];
    __shared__ int cnt[Nn];
    int tid = threadIdx.x;
    double s_lse1 = 0, s_phi1 = 0, s_lse2 = 0, s_phi2 = 0;
    for (int i = tid; i < Nn; i += 512) {
        s_lse1 += (double)g_lse1[i];
        s_phi1 += (double)g_phi1[i];
        s_lse2 += (double)g_lse2[i];
        s_phi2 += (double)g_phi2[i];
    }
    for (int i = tid; i < Nn; i += 512) cnt[i] = 0;
    __syncthreads();
    for (int i = tid; i < Nn; i += 512) atomicAdd(&cnt[g_idx[i]], 1);
    __syncthreads();
    double ent = 0;
    for (int i = tid; i < Nn; i += 512) {
        int c = cnt[i];
        if (c > 0) { float em = (float)c / (float)Nn; ent += (double)(em * logf(em + 1e-10f)); }
    }
    double vals[5] = {s_lse1, s_phi1, s_lse2, s_phi2, ent};
    for (int v = 0; v < 5; ++v) {
        red[tid] = vals[v]; __syncthreads();
        for (int s = 256; s > 0; s >>= 1) { if (tid < s) red[tid] += red[tid + s]; __syncthreads(); }
        vals[v] = red[0]; __syncthreads();
    }
    if (tid == 0) {
        double n = (double)Nn;
        double loss1 = (-0.1*vals[0] + vals[1]) / n;
        double loss2 = (-0.1*vals[2]) / n + 0.1*log(n) + vals[3]/n;
        out[2*OUTPLANE]     = (float)(0.25*(loss1 + loss2));
        out[2*OUTPLANE + 1] = (float)exp(-vals[4]);
    }
}

// ---------------- k5: write z_q and z_q_noise ----------------
__global__ void k5(const float* __restrict__ z, const float* __restrict__ codebook,
                   float* __restrict__ out) {
    int o = blockIdx.x*256 + threadIdx.x;  // 0..262143, layout ((b*64+c)*16+h)*16+w
    int w = o & 15, h = (o >> 4) & 15, c = (o >> 8) & 63, b = o >> 14;
    int i = (h*16 + w)*16 + b;
    out[o] = codebook[(g_idx[i] >> 3)*(2*Dd) + c];
    out[OUTPLANE + o] = z[o];
}

// ---------------- launch ----------------
extern "C" void kernel_launch(void* const* d_in, const int* in_sizes, int n_in,
                              void* d_out, int out_size) {
    const float* z        = (const float*)d_in[0];
    const float* codebook = (const float*)d_in[1];
    // d_in[2] = codebook_weight: unused by the reference
    const float* w1       = (const float*)d_in[3];
    const float* b1       = (const float*)d_in[4];
    const float* w2       = (const float*)d_in[5];
    const float* b2       = (const float*)d_in[6];
    const float* noise    = (const float*)d_in[7];
    float* out = (float*)d_out;

    cudaFuncSetAttribute(k2, cudaFuncAttributeMaxDynamicSharedMemorySize, SMEM_FLOATS*4);

    k0<<<1, 64>>>(w1, b1, w2, b2);
    {
        dim3 g(8, 32), bdim(32, 8);
        k_tr<<<g, bdim>>>(z);
    }
    k1<<<Nn/4, 128>>>(codebook, noise);
    {
        dim3 g(NRB, NCB);
        k2<<<g, 256, SMEM_FLOATS*4>>>();
    }
    k3<<<Nn/256, 256>>>();
    k4<<<1, 512>>>(out);
    k5<<<OUTPLANE/256, 256>>>(z, codebook, out);
}

// round 2
// speedup vs baseline: 1.2672x; 1.2672x over previous
#include <cuda_runtime.h>
#include <math.h>

// ---------------- problem constants ----------------
#define Nn 4096           // n = B*H*W
#define Dd 64             // latent dim
#define HKk 256
#define BM 128            // rows per block
#define BN 128            // cols per tile
#define NRB 32            // row blocks (N/BM)
#define NCB 4             // column chunks
#define CHUNK 1024        // cols per chunk
#define TPC 8             // tiles per chunk
#define OUTPLANE 262144   // B*C*H*W
#define L2E10 14.426950408889634f   // 10 * log2(e)  (epsilon = 0.1)
#define LN2 0.6931471805599453f

// ---------------- static device scratch ----------------
__device__ float g_zf[Nn*Dd];
__device__ float g_zs[Nn*Dd];
__device__ float g_zf2[Nn], g_zs2[Nn], g_phi1[Nn], g_phi2[Nn];
__device__ float g_w1m[Dd], g_w2m[Dd], g_b1m, g_b2m;
__device__ float g_sh1, g_sh2;     // L2E10 * max(phi1), L2E10 * max(phi2)
__device__ float g_r_m[NCB*Nn], g_r_s[NCB*Nn], g_r_bc[NCB*Nn];
__device__ int   g_r_bj[NCB*Nn];
__device__ float g_c_m[NRB*Nn], g_c_s[NRB*Nn];
__device__ int   g_idx[Nn];
__device__ float g_lse1[Nn], g_lse2[Nn];

// ---------------- FMA-pipe exp2 (no MUFU). valid for x <= ~+1; clamps low ----------------
__device__ __forceinline__ float fexp2(float x) {
    float t  = fmaxf(x, -126.0f);
    float tb = t + 12582912.0f;              // round-to-nearest int via magic
    int   ni = __float_as_int(tb);
    float r  = tb - 12582912.0f;
    float f  = t - r;                        // f in [-0.5, 0.5]
    float p  = 0.00133335581f;
    p = fmaf(p, f, 0.00961812910f);
    p = fmaf(p, f, 0.0555041087f);
    p = fmaf(p, f, 0.240226507f);
    p = fmaf(p, f, 0.693147180f);
    p = fmaf(p, f, 1.0f);
    float sc = __int_as_float((ni + (127 - 0x4B400000)) << 23);  // 2^round(t)
    return p * sc;
}

// ---------------- k0: column-means of w1/w2 and means of b1/b2 ----------------
__global__ void k0(const float* __restrict__ w1, const float* __restrict__ b1,
                   const float* __restrict__ w2, const float* __restrict__ b2) {
    int d = threadIdx.x;
    if (d < Dd) {
        float s1 = 0.f, s2 = 0.f;
        for (int k = 0; k < HKk; ++k) { s1 += w1[d*HKk + k]; s2 += w2[d*HKk + k]; }
        g_w1m[d] = s1 / (float)HKk;
        g_w2m[d] = s2 / (float)HKk;
    }
    if (d == 0) { float s = 0.f; for (int k = 0; k < HKk; ++k) s += b1[k]; g_b1m = s / (float)HKk; }
    if (d == 1) { float s = 0.f; for (int k = 0; k < HKk; ++k) s += b2[k]; g_b2m = s / (float)HKk; }
}

// ---------------- k_tr: transpose z (1024 x 256) -> zf (4096 x 64) ----------------
__global__ void k_tr(const float* __restrict__ z) {
    __shared__ float t[32][33];
    int bx = blockIdx.x, by = blockIdx.y;
    int x = bx*32 + threadIdx.x;
    #pragma unroll
    for (int q = 0; q < 4; ++q) {
        int row = by*32 + threadIdx.y + q*8;
        t[threadIdx.y + q*8][threadIdx.x] = z[row*256 + x];
    }
    __syncthreads();
    #pragma unroll
    for (int q = 0; q < 4; ++q) {
        int col = bx*32 + threadIdx.y + q*8;
        int row = by*32 + threadIdx.x;
        g_zf[col*1024 + row] = t[threadIdx.x][threadIdx.y + q*8];
    }
}

// ---------------- k1: zs, norms, phi1/phi2 ----------------
__global__ void k1(const float* __restrict__ codebook, const float* __restrict__ noise) {
    int warp = threadIdx.x >> 5, lane = threadIdx.x & 31;
    int row = blockIdx.x*4 + warp;
    const float* crow = codebook + (row >> 3) * (2*Dd);
    const float* nrow = noise + row*Dd;
    const float* frow = g_zf + row*Dd;
    float zs2 = 0.f, p1 = 0.f, zf2 = 0.f, p2 = 0.f;
    #pragma unroll
    for (int q = 0; q < 2; ++q) {
        int d = lane + q*32;
        float mu  = crow[d];
        float cov = expf(crow[Dd + d]);
        float zs  = mu + cov * nrow[d];
        g_zs[row*Dd + d] = zs;
        zs2 += zs*zs;
        p1  += zs * g_w1m[d];
        float zf = frow[d];
        zf2 += zf*zf;
        p2  += zf * g_w2m[d];
    }
    #pragma unroll
    for (int o = 16; o > 0; o >>= 1) {
        zs2 += __shfl_xor_sync(0xffffffffu, zs2, o);
        p1  += __shfl_xor_sync(0xffffffffu, p1,  o);
        zf2 += __shfl_xor_sync(0xffffffffu, zf2, o);
        p2  += __shfl_xor_sync(0xffffffffu, p2,  o);
    }
    if (lane == 0) {
        g_zs2[row] = zs2;  g_phi1[row] = p1 + g_b1m;
        g_zf2[row] = zf2;  g_phi2[row] = p2 + g_b2m;
    }
}

// ---------------- k1b: global maxes of phi1/phi2 (for safe fixed shifts) ----------------
__global__ void k1b() {
    __shared__ float m1[256], m2[256];
    int tid = threadIdx.x;
    float a = -3e38f, b = -3e38f;
    for (int i = tid; i < Nn; i += 256) { a = fmaxf(a, g_phi1[i]); b = fmaxf(b, g_phi2[i]); }
    m1[tid] = a; m2[tid] = b; __syncthreads();
    for (int s = 128; s > 0; s >>= 1) {
        if (tid < s) { m1[tid] = fmaxf(m1[tid], m1[tid+s]); m2[tid] = fmaxf(m2[tid], m2[tid+s]); }
        __syncthreads();
    }
    if (tid == 0) { g_sh1 = L2E10 * m1[0]; g_sh2 = L2E10 * m2[0]; }
}

// ---------------- k2: fused cost GEMM + argmax + row/col exp-sums (log2 domain) ----------------
// smem (floats): zfs[0,8192) K-major | zss[8192,16384) K-major |
//                zf2s[16384..+128) lp2s[..+128) nzs2[..+128) lp1s[..+128)
#define SMEM_FLOATS 16896
__global__ void __launch_bounds__(256, 1) k2() {
    extern __shared__ float sm[];
    float* zfs  = sm;
    float* zss  = sm + 8192;
    float* zf2s = sm + 16384;
    float* lp2s = zf2s + 128;   // L2E10 * phi2 for block rows
    float* nzs2 = lp2s + 128;   // -zs2 for tile cols
    float* lp1s = nzs2 + 128;   // L2E10 * phi1 for tile cols

    const int tid = threadIdx.x;
    const int tx = tid & 15, ty = tid >> 4;
    const int rb = blockIdx.x, cb = blockIdx.y;
    const int i0 = rb * BM;
    const float S1g = g_sh1, S2g = g_sh2;

    // block loads: zf tile (K-major) + row-side scalars
    for (int t = tid; t < 128*16; t += 256) {
        int r = t >> 4, d4 = t & 15;
        float4 v = ((const float4*)g_zf)[(i0 + r)*16 + d4];
        zfs[(d4*4+0)*BM + r] = v.x;
        zfs[(d4*4+1)*BM + r] = v.y;
        zfs[(d4*4+2)*BM + r] = v.z;
        zfs[(d4*4+3)*BM + r] = v.w;
    }
    if (tid < BM) { zf2s[tid] = g_zf2[i0 + tid]; lp2s[tid] = L2E10 * g_phi2[i0 + tid]; }
    __syncthreads();

    // per-thread row constants (stable across tiles)
    float nzf[8], lph2[8];
    #pragma unroll
    for (int r = 0; r < 8; ++r) { nzf[r] = -zf2s[ty*8 + r]; lph2[r] = lp2s[ty*8 + r]; }

    // row state
    float bq[8], rs[8], shift1[8]; int bj[8];
    #pragma unroll
    for (int r = 0; r < 8; ++r) { bq[r] = -3e38f; rs[r] = 0.f; shift1[r] = -1e30f; bj[r] = 0x7fffffff; }

    for (int tile = 0; tile < TPC; ++tile) {
        const int j0 = cb*CHUNK + tile*BN;
        __syncthreads();  // previous flush readers done with zss
        for (int t = tid; t < 128*16; t += 256) {
            int c = t >> 4, d4 = t & 15;
            float4 v = ((const float4*)g_zs)[(j0 + c)*16 + d4];
            zss[(d4*4+0)*BN + c] = v.x;
            zss[(d4*4+1)*BN + c] = v.y;
            zss[(d4*4+2)*BN + c] = v.z;
            zss[(d4*4+3)*BN + c] = v.w;
        }
        if (tid < BN) { nzs2[tid] = -g_zs2[j0 + tid]; lp1s[tid] = L2E10 * g_phi1[j0 + tid]; }
        __syncthreads();

        // ---- GEMM ----
        float acc[8][8];
        #pragma unroll
        for (int r = 0; r < 8; ++r)
            #pragma unroll
            for (int c = 0; c < 8; ++c) acc[r][c] = 0.f;

        #pragma unroll 8
        for (int k = 0; k < Dd; ++k) {
            const float4 a0 = *(const float4*)(zfs + k*BM + ty*8);
            const float4 a1 = *(const float4*)(zfs + k*BM + ty*8 + 4);
            const float4 b0 = *(const float4*)(zss + k*BN + tx*8);
            const float4 b1 = *(const float4*)(zss + k*BN + tx*8 + 4);
            float av[8] = {a0.x, a0.y, a0.z, a0.w, a1.x, a1.y, a1.z, a1.w};
            float bv[8] = {b0.x, b0.y, b0.z, b0.w, b1.x, b1.y, b1.z, b1.w};
            #pragma unroll
            for (int r = 0; r < 8; ++r)
                #pragma unroll
                for (int c = 0; c < 8; ++c)
                    acc[r][c] += av[r] * bv[c];
        }

        // ---- pass 1: c2 = -cost, row argmax (running), tile col max ----
        float nz[8], lp1[8];
        #pragma unroll
        for (int c = 0; c < 8; ++c) { nz[c] = nzs2[tx*8 + c]; lp1[c] = lp1s[tx*8 + c]; }
        float cmax[8];
        #pragma unroll
        for (int c = 0; c < 8; ++c) cmax[c] = -3e38f;

        #pragma unroll
        for (int r = 0; r < 8; ++r) {
            const float nf = nzf[r];
            #pragma unroll
            for (int c = 0; c < 8; ++c) {
                float c2 = fmaf(2.0f, acc[r][c], nz[c] + nf);   // = -cost
                acc[r][c] = c2;
                if (c2 > bq[r]) { bq[r] = c2; bj[r] = j0 + tx*8 + c; }
                cmax[c] = fmaxf(cmax[c], c2);
            }
        }

        // ---- shifts (fixed for this tile) + row rescale ----
        float sh2[8], cs[8];
        #pragma unroll
        for (int c = 0; c < 8; ++c) { sh2[c] = fmaf(L2E10, cmax[c], S2g); cs[c] = 0.f; }
        #pragma unroll
        for (int r = 0; r < 8; ++r) {
            float ns = fmaf(L2E10, bq[r], S1g);
            rs[r] *= fexp2(shift1[r] - ns);
            shift1[r] = ns;
        }

        // ---- pass 2: branchless exp sums ----
        #pragma unroll
        for (int r = 0; r < 8; ++r) {
            float pp[8], qq[8];
            #pragma unroll
            for (int c = 0; c < 8; ++c) { pp[c] = lp1[c] - shift1[r]; qq[c] = lph2[r] - sh2[c]; }
            #pragma unroll
            for (int c = 0; c < 8; ++c) {
                float c2 = acc[r][c];
                rs[r] += fexp2(fmaf(L2E10, c2, pp[c]));
                cs[c] += fexp2(fmaf(L2E10, c2, qq[c]));
            }
        }

        // ---- column flush: reduce 16 (m,s) partials per column (log2 domain) ----
        __syncthreads();
        float* redm = zss;
        float* reds = zss + 2048;
        #pragma unroll
        for (int c = 0; c < 8; ++c) {
            redm[(tx*8 + c)*16 + ty] = sh2[c];
            reds[(tx*8 + c)*16 + ty] = cs[c];
        }
        __syncthreads();
        if (tid < BN) {
            float m = -3e38f, s = 0.f;
            #pragma unroll
            for (int t = 0; t < 16; ++t) {
                float mm = redm[tid*16 + t], ss = reds[tid*16 + t];
                if (mm > m) { s = s*fexp2(m - mm) + ss; m = mm; }
                else        { s += ss*fexp2(mm - m); }
            }
            g_c_m[rb*Nn + j0 + tid] = m;
            g_c_s[rb*Nn + j0 + tid] = s;
        }
    }

    // ---- row flush: reduce 16 partials per row ----
    __syncthreads();
    float* rrm = zss;
    float* rrs = zss + 2048;
    float* rrb = zss + 4096;
    int*   rrj = (int*)(zss + 6144);
    #pragma unroll
    for (int r = 0; r < 8; ++r) {
        int pos = (ty*8 + r)*16 + tx;
        rrm[pos] = shift1[r]; rrs[pos] = rs[r]; rrb[pos] = bq[r]; rrj[pos] = bj[r];
    }
    __syncthreads();
    if (tid < BM) {
        float m = -3e38f, s = 0.f, bqv = -3e38f; int bjv = 0x7fffffff;
        #pragma unroll
        for (int t = 0; t < 16; ++t) {
            float mm = rrm[tid*16 + t], ss = rrs[tid*16 + t];
            if (mm > m) { s = s*fexp2(m - mm) + ss; m = mm; }
            else        { s += ss*fexp2(mm - m); }
            float bb = rrb[tid*16 + t]; int jj = rrj[tid*16 + t];
            if (bb > bqv || (bb == bqv && jj < bjv)) { bqv = bb; bjv = jj; }
        }
        g_r_m [cb*Nn + i0 + tid] = m;
        g_r_s [cb*Nn + i0 + tid] = s;
        g_r_bc[cb*Nn + i0 + tid] = bqv;
        g_r_bj[cb*Nn + i0 + tid] = bjv;
    }
}

// ---------------- k3: merge partials (log2 domain) -> lse (ln), idx ----------------
__global__ void k3() {
    int i = blockIdx.x*blockDim.x + threadIdx.x;
    float m = -3e38f, s = 0.f, bqv = -3e38f; int bjv = 0x7fffffff;
    #pragma unroll
    for (int c = 0; c < NCB; ++c) {
        float mm = g_r_m[c*Nn + i], ss = g_r_s[c*Nn + i];
        if (mm > m) { s = s*fexp2(m - mm) + ss; m = mm; }
        else        { s += ss*fexp2(mm - m); }
        float bb = g_r_bc[c*Nn + i]; int jj = g_r_bj[c*Nn + i];
        if (bb > bqv || (bb == bqv && jj < bjv)) { bqv = bb; bjv = jj; }
    }
    g_lse1[i] = LN2*(m + log2f(s)) - logf((float)Nn);
    g_idx[i] = bjv;
    m = -3e38f; s = 0.f;
    #pragma unroll
    for (int r = 0; r < NRB; ++r) {
        float mm = g_c_m[r*Nn + i], ss = g_c_s[r*Nn + i];
        if (mm > m) { s = s*fexp2(m - mm) + ss; m = mm; }
        else        { s += ss*fexp2(mm - m); }
    }
    g_lse2[i] = LN2*(m + log2f(s));
}

// ---------------- k4: loss + perplexity ----------------
__global__ void k4(float* __restrict__ out) {
    __shared__ double red[512];
    __shared__ int cnt[Nn];
    int tid = threadIdx.x;
    double s_lse1 = 0, s_phi1 = 0, s_lse2 = 0, s_phi2 = 0;
    for (int i = tid; i < Nn; i += 512) {
        s_lse1 += (double)g_lse1[i];
        s_phi1 += (double)g_phi1[i];
        s_lse2 += (double)g_lse2[i];
        s_phi2 += (double)g_phi2[i];
    }
    for (int i = tid; i < Nn; i += 512) cnt[i] = 0;
    __syncthreads();
    for (int i = tid; i < Nn; i += 512) atomicAdd(&cnt[g_idx[i]], 1);
    __syncthreads();
    double ent = 0;
    for (int i = tid; i < Nn; i += 512) {
        int c = cnt[i];
        if (c > 0) { float em = (float)c / (float)Nn; ent += (double)(em * logf(em + 1e-10f)); }
    }
    double vals[5] = {s_lse1, s_phi1, s_lse2, s_phi2, ent};
    for (int v = 0; v < 5; ++v) {
        red[tid] = vals[v]; __syncthreads();
        for (int s = 256; s > 0; s >>= 1) { if (tid < s) red[tid] += red[tid + s]; __syncthreads(); }
        vals[v] = red[0]; __syncthreads();
    }
    if (tid == 0) {
        double n = (double)Nn;
        double loss1 = (-0.1*vals[0] + vals[1]) / n;
        double loss2 = (-0.1*vals[2]) / n + 0.1*log(n) + vals[3]/n;
        out[2*OUTPLANE]     = (float)(0.25*(loss1 + loss2));
        out[2*OUTPLANE + 1] = (float)exp(-vals[4]);
    }
}

// ---------------- k5: write z_q and z_q_noise ----------------
__global__ void k5(const float* __restrict__ z, const float* __restrict__ codebook,
                   float* __restrict__ out) {
    int o = blockIdx.x*256 + threadIdx.x;
    int w = o & 15, h = (o >> 4) & 15, c = (o >> 8) & 63, b = o >> 14;
    int i = (h*16 + w)*16 + b;
    out[o] = codebook[(g_idx[i] >> 3)*(2*Dd) + c];
    out[OUTPLANE + o] = z[o];
}

// ---------------- launch ----------------
extern "C" void kernel_launch(void* const* d_in, const int* in_sizes, int n_in,
                              void* d_out, int out_size) {
    const float* z        = (const float*)d_in[0];
    const float* codebook = (const float*)d_in[1];
    const float* w1       = (const float*)d_in[3];
    const float* b1       = (const float*)d_in[4];
    const float* w2       = (const float*)d_in[5];
    const float* b2       = (const float*)d_in[6];
    const float* noise    = (const float*)d_in[7];
    float* out = (float*)d_out;

    cudaFuncSetAttribute(k2, cudaFuncAttributeMaxDynamicSharedMemorySize, SMEM_FLOATS*4);

    k0<<<1, 64>>>(w1, b1, w2, b2);
    {
        dim3 g(8, 32), bdim(32, 8);
        k_tr<<<g, bdim>>>(z);
    }
    k1<<<Nn/4, 128>>>(codebook, noise);
    k1b<<<1, 256>>>();
    {
        dim3 g(NRB, NCB);
        k2<<<g, 256, SMEM_FLOATS*4>>>();
    }
    k3<<<Nn/256, 256>>>();
    k4<<<1, 512>>>(out);
    k5<<<OUTPLANE/256, 256>>>(z, codebook, out);
}

// round 3
// speedup vs baseline: 1.3618x; 1.0746x over previous
#include <cuda_runtime.h>
#include <math.h>
#include <string.h>

// ---------------- problem constants ----------------
#define Nn 4096
#define Dd 64
#define HKk 256
#define BM 128
#define BN 128
#define NRB 32
#define NCB 4
#define CHUNK 1024
#define TPC 8
#define OUTPLANE 262144
#define L2E10 14.426950408889634f   // 10 * log2(e)
#define LN2 0.6931471805599453f

typedef unsigned long long ull;

// ---------------- static device scratch ----------------
__device__ float g_zf[Nn*Dd];
__device__ float g_zs[Nn*Dd];
__device__ float g_zf2[Nn], g_zs2[Nn], g_phi1[Nn], g_phi2[Nn];
__device__ float g_w1m[Dd], g_w2m[Dd], g_b1m, g_b2m;
__device__ unsigned g_aph1, g_aph2;          // ordered-encoded max(phi1/phi2)
__device__ float g_r_m[NCB*Nn], g_r_s[NCB*Nn], g_r_bc[NCB*Nn];
__device__ int   g_r_bj[NCB*Nn];
__device__ float g_c_m[NRB*Nn], g_c_s[NRB*Nn];
__device__ int   g_idx[Nn];
__device__ float g_lse1[Nn], g_lse2[Nn];

// ---------------- f32x2 packed helpers ----------------
#define FMA2(d,a,b,c) asm("fma.rn.f32x2 %0, %1, %2, %3;" : "=l"(d) : "l"(a), "l"(b), "l"(c))
#define ADD2(d,a,b)   asm("add.rn.f32x2 %0, %1, %2;"     : "=l"(d) : "l"(a), "l"(b))
#define MUL2(d,a,b)   asm("mul.rn.f32x2 %0, %1, %2;"     : "=l"(d) : "l"(a), "l"(b))

__device__ __forceinline__ ull dup2(float x) {
    ull r; asm("mov.b64 %0, {%1, %1};" : "=l"(r) : "f"(x)); return r;
}
__device__ __forceinline__ ull pk2(float lo, float hi) {
    ull r; asm("mov.b64 %0, {%1, %2};" : "=l"(r) : "f"(lo), "f"(hi)); return r;
}
__device__ __forceinline__ float2 asf2(ull v) {
    float2 f; asm("mov.b64 {%0, %1}, %2;" : "=f"(f.x), "=f"(f.y) : "l"(v)); return f;
}

// packed exp2 constants, built once per kernel
struct PC { ull MAG, NMAG, NEG1, C5, C4, C3, C2, C1, ONE, L2, TWO; };
__device__ __forceinline__ PC make_pc() {
    PC K;
    K.MAG  = dup2(12582912.0f);
    K.NMAG = dup2(-12582912.0f);
    K.NEG1 = dup2(-1.0f);
    K.C5   = dup2(0.00133335581f);
    K.C4   = dup2(0.00961812910f);
    K.C3   = dup2(0.0555041087f);
    K.C2   = dup2(0.240226507f);
    K.C1   = dup2(0.693147180f);
    K.ONE  = dup2(1.0f);
    K.L2   = dup2(L2E10);
    K.TWO  = dup2(2.0f);
    return K;
}

// acc += exp2(t) for both packed lanes; underflow -> exact 0 via int clamp
__device__ __forceinline__ void pexp2acc(ull &acc, ull t, const PC& K) {
    ull tb; ADD2(tb, t, K.MAG);
    ull rr; ADD2(rr, tb, K.NMAG);
    ull f;  FMA2(f, rr, K.NEG1, t);       // f = t - round(t)
    ull p = K.C5;
    FMA2(p, p, f, K.C4);
    FMA2(p, p, f, K.C3);
    FMA2(p, p, f, K.C2);
    FMA2(p, p, f, K.C1);
    FMA2(p, p, f, K.ONE);
    int elo = (int)(unsigned)tb        + (127 - 0x4B400000);
    int ehi = (int)(unsigned)(tb >> 32) + (127 - 0x4B400000);
    elo = elo < 0 ? 0 : elo;
    ehi = ehi < 0 ? 0 : ehi;
    ull sc = pk2(__int_as_float(elo << 23), __int_as_float(ehi << 23));
    FMA2(acc, p, sc, acc);
}

// scalar exp2 on FMA pipe (flushes / merges)
__device__ __forceinline__ float fexp2(float x) {
    float t  = fmaxf(x, -126.0f);
    float tb = t + 12582912.0f;
    int   ni = __float_as_int(tb);
    float r  = tb - 12582912.0f;
    float f  = t - r;
    float p  = 0.00133335581f;
    p = fmaf(p, f, 0.00961812910f);
    p = fmaf(p, f, 0.0555041087f);
    p = fmaf(p, f, 0.240226507f);
    p = fmaf(p, f, 0.693147180f);
    p = fmaf(p, f, 1.0f);
    float sc = __int_as_float((ni + (127 - 0x4B400000)) << 23);
    return p * sc;
}

// ordered float<->uint for atomicMax on floats
__device__ __forceinline__ unsigned fenc(float f) {
    unsigned u = __float_as_uint(f);
    return (u & 0x80000000u) ? ~u : (u | 0x80000000u);
}
__device__ __forceinline__ float fdec(unsigned u) {
    return (u & 0x80000000u) ? __uint_as_float(u & 0x7fffffffu) : __uint_as_float(~u);
}

// ---------------- k0: w/b means + atomic init ----------------
__global__ void k0(const float* __restrict__ w1, const float* __restrict__ b1,
                   const float* __restrict__ w2, const float* __restrict__ b2) {
    int d = threadIdx.x;
    if (d < Dd) {
        float s1 = 0.f, s2 = 0.f;
        for (int k = 0; k < HKk; ++k) { s1 += w1[d*HKk + k]; s2 += w2[d*HKk + k]; }
        g_w1m[d] = s1 / (float)HKk;
        g_w2m[d] = s2 / (float)HKk;
    }
    if (d == 0) { float s = 0.f; for (int k = 0; k < HKk; ++k) s += b1[k]; g_b1m = s / (float)HKk; g_aph1 = 0u; }
    if (d == 1) { float s = 0.f; for (int k = 0; k < HKk; ++k) s += b2[k]; g_b2m = s / (float)HKk; g_aph2 = 0u; }
}

// ---------------- k_tr: transpose z (1024 x 256) -> zf (4096 x 64) ----------------
__global__ void k_tr(const float* __restrict__ z) {
    __shared__ float t[32][33];
    int bx = blockIdx.x, by = blockIdx.y;
    int x = bx*32 + threadIdx.x;
    #pragma unroll
    for (int q = 0; q < 4; ++q) {
        int row = by*32 + threadIdx.y + q*8;
        t[threadIdx.y + q*8][threadIdx.x] = z[row*256 + x];
    }
    __syncthreads();
    #pragma unroll
    for (int q = 0; q < 4; ++q) {
        int col = bx*32 + threadIdx.y + q*8;
        int row = by*32 + threadIdx.x;
        g_zf[col*1024 + row] = t[threadIdx.x][threadIdx.y + q*8];
    }
}

// ---------------- k1: zs, norms, phi1/phi2 (+ atomic global phi-max) ----------------
__global__ void k1(const float* __restrict__ codebook, const float* __restrict__ noise) {
    int warp = threadIdx.x >> 5, lane = threadIdx.x & 31;
    int row = blockIdx.x*4 + warp;
    const float* crow = codebook + (row >> 3) * (2*Dd);
    const float* nrow = noise + row*Dd;
    const float* frow = g_zf + row*Dd;
    float zs2 = 0.f, p1 = 0.f, zf2 = 0.f, p2 = 0.f;
    #pragma unroll
    for (int q = 0; q < 2; ++q) {
        int d = lane + q*32;
        float mu  = crow[d];
        float cov = expf(crow[Dd + d]);
        float zs  = mu + cov * nrow[d];
        g_zs[row*Dd + d] = zs;
        zs2 += zs*zs;
        p1  += zs * g_w1m[d];
        float zf = frow[d];
        zf2 += zf*zf;
        p2  += zf * g_w2m[d];
    }
    #pragma unroll
    for (int o = 16; o > 0; o >>= 1) {
        zs2 += __shfl_xor_sync(0xffffffffu, zs2, o);
        p1  += __shfl_xor_sync(0xffffffffu, p1,  o);
        zf2 += __shfl_xor_sync(0xffffffffu, zf2, o);
        p2  += __shfl_xor_sync(0xffffffffu, p2,  o);
    }
    if (lane == 0) {
        float phi1 = p1 + g_b1m, phi2 = p2 + g_b2m;
        g_zs2[row] = zs2;  g_phi1[row] = phi1;
        g_zf2[row] = zf2;  g_phi2[row] = phi2;
        atomicMax(&g_aph1, fenc(phi1));
        atomicMax(&g_aph2, fenc(phi2));
    }
}

// ---------------- k2: fused cost GEMM (f32x2) + argmax + packed exp-sums ----------------
#define SMEM_FLOATS 16896
__global__ void __launch_bounds__(256, 1) k2() {
    extern __shared__ float sm[];
    float* zfs  = sm;
    float* zss  = sm + 8192;
    float* zf2s = sm + 16384;
    float* lp2s = zf2s + 128;
    float* nzs2 = lp2s + 128;
    float* lp1s = nzs2 + 128;

    const int tid = threadIdx.x;
    const int tx = tid & 15, ty = tid >> 4;
    const int rb = blockIdx.x, cb = blockIdx.y;
    const int i0 = rb * BM;
    const float S1g = L2E10 * fdec(g_aph1);
    const float S2g = L2E10 * fdec(g_aph2);
    const PC K = make_pc();

    for (int t = tid; t < 128*16; t += 256) {
        int r = t >> 4, d4 = t & 15;
        float4 v = ((const float4*)g_zf)[(i0 + r)*16 + d4];
        zfs[(d4*4+0)*BM + r] = v.x;
        zfs[(d4*4+1)*BM + r] = v.y;
        zfs[(d4*4+2)*BM + r] = v.z;
        zfs[(d4*4+3)*BM + r] = v.w;
    }
    if (tid < BM) { zf2s[tid] = g_zf2[i0 + tid]; lp2s[tid] = L2E10 * g_phi2[i0 + tid]; }
    __syncthreads();

    float nzf[8], lph2[8];
    #pragma unroll
    for (int r = 0; r < 8; ++r) { nzf[r] = -zf2s[ty*8 + r]; lph2[r] = lp2s[ty*8 + r]; }

    // row state (packed sums)
    float bq[8], shift1[8]; int bj[8]; ull rs2[8];
    #pragma unroll
    for (int r = 0; r < 8; ++r) { bq[r] = -3e38f; rs2[r] = 0ull; shift1[r] = -1e30f; bj[r] = 0x7fffffff; }

    for (int tile = 0; tile < TPC; ++tile) {
        const int j0 = cb*CHUNK + tile*BN;
        __syncthreads();
        for (int t = tid; t < 128*16; t += 256) {
            int c = t >> 4, d4 = t & 15;
            float4 v = ((const float4*)g_zs)[(j0 + c)*16 + d4];
            zss[(d4*4+0)*BN + c] = v.x;
            zss[(d4*4+1)*BN + c] = v.y;
            zss[(d4*4+2)*BN + c] = v.z;
            zss[(d4*4+3)*BN + c] = v.w;
        }
        if (tid < BN) { nzs2[tid] = -g_zs2[j0 + tid]; lp1s[tid] = L2E10 * g_phi1[j0 + tid]; }
        __syncthreads();

        // ---- GEMM: packed accumulators over column pairs ----
        ull acc2[8][4];
        #pragma unroll
        for (int r = 0; r < 8; ++r)
            #pragma unroll
            for (int cc = 0; cc < 4; ++cc) acc2[r][cc] = 0ull;

        #pragma unroll 4
        for (int k = 0; k < Dd; ++k) {
            const float4 a0 = *(const float4*)(zfs + k*BM + ty*8);
            const float4 a1 = *(const float4*)(zfs + k*BM + ty*8 + 4);
            const ulonglong2 bA = *(const ulonglong2*)(zss + k*BN + tx*8);
            const ulonglong2 bB = *(const ulonglong2*)(zss + k*BN + tx*8 + 4);
            const ull bv0 = bA.x, bv1 = bA.y, bv2 = bB.x, bv3 = bB.y;
            float av[8] = {a0.x, a0.y, a0.z, a0.w, a1.x, a1.y, a1.z, a1.w};
            #pragma unroll
            for (int r = 0; r < 8; ++r) {
                ull ar = dup2(av[r]);
                FMA2(acc2[r][0], ar, bv0, acc2[r][0]);
                FMA2(acc2[r][1], ar, bv1, acc2[r][1]);
                FMA2(acc2[r][2], ar, bv2, acc2[r][2]);
                FMA2(acc2[r][3], ar, bv3, acc2[r][3]);
            }
        }

        // ---- pass 1: c2 = -cost (packed), row argmax + col max (scalar compares) ----
        const ulonglong2 zA = *(const ulonglong2*)(nzs2 + tx*8);
        const ulonglong2 zB = *(const ulonglong2*)(nzs2 + tx*8 + 4);
        ull nzp2[4] = {zA.x, zA.y, zB.x, zB.y};
        const ulonglong2 lA = *(const ulonglong2*)(lp1s + tx*8);
        const ulonglong2 lB = *(const ulonglong2*)(lp1s + tx*8 + 4);
        ull lp1p2[4] = {lA.x, lA.y, lB.x, lB.y};

        float cmax[8];
        #pragma unroll
        for (int c = 0; c < 8; ++c) cmax[c] = -3e38f;

        #pragma unroll
        for (int r = 0; r < 8; ++r) {
            ull nfr = dup2(nzf[r]);
            #pragma unroll
            for (int cc = 0; cc < 4; ++cc) {
                ull t; ADD2(t, nzp2[cc], nfr);
                FMA2(t, acc2[r][cc], K.TWO, t);   // c2 = 2*dot - zs2 - zf2
                acc2[r][cc] = t;
                float2 f = asf2(t);
                if (f.x > bq[r]) { bq[r] = f.x; bj[r] = j0 + tx*8 + 2*cc; }
                if (f.y > bq[r]) { bq[r] = f.y; bj[r] = j0 + tx*8 + 2*cc + 1; }
                cmax[2*cc]   = fmaxf(cmax[2*cc],   f.x);
                cmax[2*cc+1] = fmaxf(cmax[2*cc+1], f.y);
            }
        }

        // ---- shifts + row rescale ----
        float sh2[8];
        #pragma unroll
        for (int c = 0; c < 8; ++c) sh2[c] = fmaf(L2E10, cmax[c], S2g);
        ull cs2[4];
        #pragma unroll
        for (int cc = 0; cc < 4; ++cc) cs2[cc] = 0ull;
        #pragma unroll
        for (int r = 0; r < 8; ++r) {
            float ns = fmaf(L2E10, bq[r], S1g);
            float rsc = fexp2(shift1[r] - ns);
            ull rscp = dup2(rsc);
            MUL2(rs2[r], rs2[r], rscp);
            shift1[r] = ns;
        }

        // ---- pass 2: packed exp sums ----
        ull nsh2p2[4];
        #pragma unroll
        for (int cc = 0; cc < 4; ++cc) nsh2p2[cc] = pk2(-sh2[2*cc], -sh2[2*cc+1]);

        #pragma unroll
        for (int r = 0; r < 8; ++r) {
            ull m1r = dup2(-shift1[r]);
            ull p2r = dup2(lph2[r]);
            #pragma unroll
            for (int cc = 0; cc < 4; ++cc) {
                ull t1; ADD2(t1, lp1p2[cc], m1r);
                FMA2(t1, acc2[r][cc], K.L2, t1);
                pexp2acc(rs2[r], t1, K);
                ull t2; ADD2(t2, nsh2p2[cc], p2r);
                FMA2(t2, acc2[r][cc], K.L2, t2);
                pexp2acc(cs2[cc], t2, K);
            }
        }

        // ---- column flush ----
        __syncthreads();
        float* redm = zss;
        float* reds = zss + 2048;
        #pragma unroll
        for (int cc = 0; cc < 4; ++cc) {
            float2 f = asf2(cs2[cc]);
            redm[(tx*8 + 2*cc  )*16 + ty] = sh2[2*cc];
            reds[(tx*8 + 2*cc  )*16 + ty] = f.x;
            redm[(tx*8 + 2*cc+1)*16 + ty] = sh2[2*cc+1];
            reds[(tx*8 + 2*cc+1)*16 + ty] = f.y;
        }
        __syncthreads();
        if (tid < BN) {
            float m = -3e38f, s = 0.f;
            #pragma unroll
            for (int t = 0; t < 16; ++t) {
                float mm = redm[tid*16 + t], ss = reds[tid*16 + t];
                if (mm > m) { s = s*fexp2(m - mm) + ss; m = mm; }
                else        { s += ss*fexp2(mm - m); }
            }
            g_c_m[rb*Nn + j0 + tid] = m;
            g_c_s[rb*Nn + j0 + tid] = s;
        }
    }

    // ---- row flush ----
    __syncthreads();
    float* rrm = zss;
    float* rrs = zss + 2048;
    float* rrb = zss + 4096;
    int*   rrj = (int*)(zss + 6144);
    #pragma unroll
    for (int r = 0; r < 8; ++r) {
        int pos = (ty*8 + r)*16 + tx;
        float2 f = asf2(rs2[r]);
        rrm[pos] = shift1[r]; rrs[pos] = f.x + f.y; rrb[pos] = bq[r]; rrj[pos] = bj[r];
    }
    __syncthreads();
    if (tid < BM) {
        float m = -3e38f, s = 0.f, bqv = -3e38f; int bjv = 0x7fffffff;
        #pragma unroll
        for (int t = 0; t < 16; ++t) {
            float mm = rrm[tid*16 + t], ss = rrs[tid*16 + t];
            if (mm > m) { s = s*fexp2(m - mm) + ss; m = mm; }
            else        { s += ss*fexp2(mm - m); }
            float bb = rrb[tid*16 + t]; int jj = rrj[tid*16 + t];
            if (bb > bqv || (bb == bqv && jj < bjv)) { bqv = bb; bjv = jj; }
        }
        g_r_m [cb*Nn + i0 + tid] = m;
        g_r_s [cb*Nn + i0 + tid] = s;
        g_r_bc[cb*Nn + i0 + tid] = bqv;
        g_r_bj[cb*Nn + i0 + tid] = bjv;
    }
}

// ---------------- k3: merge partials -> lse (ln), idx ----------------
__global__ void k3() {
    int i = blockIdx.x*blockDim.x + threadIdx.x;
    float m = -3e38f, s = 0.f, bqv = -3e38f; int bjv = 0x7fffffff;
    #pragma unroll
    for (int c = 0; c < NCB; ++c) {
        float mm = g_r_m[c*Nn + i], ss = g_r_s[c*Nn + i];
        if (mm > m) { s = s*fexp2(m - mm) + ss; m = mm; }
        else        { s += ss*fexp2(mm - m); }
        float bb = g_r_bc[c*Nn + i]; int jj = g_r_bj[c*Nn + i];
        if (bb > bqv || (bb == bqv && jj < bjv)) { bqv = bb; bjv = jj; }
    }
    g_lse1[i] = LN2*(m + log2f(s)) - logf((float)Nn);
    g_idx[i] = bjv;
    m = -3e38f; s = 0.f;
    #pragma unroll
    for (int r = 0; r < NRB; ++r) {
        float mm = g_c_m[r*Nn + i], ss = g_c_s[r*Nn + i];
        if (mm > m) { s = s*fexp2(m - mm) + ss; m = mm; }
        else        { s += ss*fexp2(mm - m); }
    }
    g_lse2[i] = LN2*(m + log2f(s));
}

// ---------------- k4: loss + perplexity ----------------
__global__ void k4(float* __restrict__ out) {
    __shared__ double red[512];
    __shared__ int cnt[Nn];
    int tid = threadIdx.x;
    double s_lse1 = 0, s_phi1 = 0, s_lse2 = 0, s_phi2 = 0;
    for (int i = tid; i < Nn; i += 512) {
        s_lse1 += (double)g_lse1[i];
        s_phi1 += (double)g_phi1[i];
        s_lse2 += (double)g_lse2[i];
        s_phi2 += (double)g_phi2[i];
    }
    for (int i = tid; i < Nn; i += 512) cnt[i] = 0;
    __syncthreads();
    for (int i = tid; i < Nn; i += 512) atomicAdd(&cnt[g_idx[i]], 1);
    __syncthreads();
    double ent = 0;
    for (int i = tid; i < Nn; i += 512) {
        int c = cnt[i];
        if (c > 0) { float em = (float)c / (float)Nn; ent += (double)(em * logf(em + 1e-10f)); }
    }
    double vals[5] = {s_lse1, s_phi1, s_lse2, s_phi2, ent};
    for (int v = 0; v < 5; ++v) {
        red[tid] = vals[v]; __syncthreads();
        for (int s = 256; s > 0; s >>= 1) { if (tid < s) red[tid] += red[tid + s]; __syncthreads(); }
        vals[v] = red[0]; __syncthreads();
    }
    if (tid == 0) {
        double n = (double)Nn;
        double loss1 = (-0.1*vals[0] + vals[1]) / n;
        double loss2 = (-0.1*vals[2]) / n + 0.1*log(n) + vals[3]/n;
        out[2*OUTPLANE]     = (float)(0.25*(loss1 + loss2));
        out[2*OUTPLANE + 1] = (float)exp(-vals[4]);
    }
}

// ---------------- k5: write z_q and z_q_noise ----------------
__global__ void k5(const float* __restrict__ z, const float* __restrict__ codebook,
                   float* __restrict__ out) {
    int o = blockIdx.x*256 + threadIdx.x;
    int w = o & 15, h = (o >> 4) & 15, c = (o >> 8) & 63, b = o >> 14;
    int i = (h*16 + w)*16 + b;
    out[o] = codebook[(g_idx[i] >> 3)*(2*Dd) + c];
    out[OUTPLANE + o] = z[o];
}

// ---------------- launch ----------------
extern "C" void kernel_launch(void* const* d_in, const int* in_sizes, int n_in,
                              void* d_out, int out_size) {
    const float* z        = (const float*)d_in[0];
    const float* codebook = (const float*)d_in[1];
    const float* w1       = (const float*)d_in[3];
    const float* b1       = (const float*)d_in[4];
    const float* w2       = (const float*)d_in[5];
    const float* b2       = (const float*)d_in[6];
    const float* noise    = (const float*)d_in[7];
    float* out = (float*)d_out;

    cudaFuncSetAttribute(k2, cudaFuncAttributeMaxDynamicSharedMemorySize, SMEM_FLOATS*4);

    k0<<<1, 64>>>(w1, b1, w2, b2);
    {
        dim3 g(8, 32), bdim(32, 8);
        k_tr<<<g, bdim>>>(z);
    }
    k1<<<Nn/4, 128>>>(codebook, noise);
    {
        dim3 g(NRB, NCB);
        k2<<<g, 256, SMEM_FLOATS*4>>>();
    }
    k3<<<Nn/256, 256>>>();
    k4<<<1, 512>>>(out);
    k5<<<OUTPLANE/256, 256>>>(z, codebook, out);
}